// round 2
// baseline (speedup 1.0000x reference)
#include <cuda_runtime.h>

#define D 128
#define MAXN 100000
#define KC 16   // K-chunk rows staged in SMEM per step

// ---------------- scratch (static device globals: allocation-free) -----------
// g_W: fused W = W_pos - softplus(W_negraw), order: 0=AB, 1=BA, 2=AA
// g_Q: Q = softmax(X_src) @ W, order: 0=Q_AB(from A), 1=Q_BA(from B), 2=Q_AA(from A)
__device__ float g_W[3][D * D];
__device__ float g_Q[3][(size_t)MAXN * D];

// packed fp32x2 FMA (sm_100a+): 2 fp32 FMAs per issue
__device__ __forceinline__ unsigned long long ffma2(unsigned long long a,
                                                    unsigned long long b,
                                                    unsigned long long c) {
    unsigned long long d;
    asm("fma.rn.f32x2 %0, %1, %2, %3;" : "=l"(d) : "l"(a), "l"(b), "l"(c));
    return d;
}

// pack scalar float into {x,x} 64-bit pair (one MOV)
__device__ __forceinline__ unsigned long long dup2(float x) {
    unsigned long long d;
    unsigned int xi = __float_as_uint(x);
    asm("mov.b64 %0, {%1, %1};" : "=l"(d) : "r"(xi));
    return d;
}

// ---------------- kernel 0: W = W_pos - softplus(W_negraw) -------------------
__global__ void compute_W_kernel(const float* __restrict__ wp0, const float* __restrict__ wn0,
                                 const float* __restrict__ wp1, const float* __restrict__ wn1,
                                 const float* __restrict__ wp2, const float* __restrict__ wn2) {
    int i = blockIdx.x * blockDim.x + threadIdx.x;
    if (i >= 3 * D * D) return;
    int m = i / (D * D), j = i % (D * D);
    const float* wp = (m == 0) ? wp0 : (m == 1 ? wp1 : wp2);
    const float* wn = (m == 0) ? wn0 : (m == 1 ? wn1 : wn2);
    float x = wn[j];
    // numerically stable softplus
    float sp = fmaxf(x, 0.0f) + log1pf(expf(-fabsf(x)));
    g_W[m][j] = wp[j] - sp;
}

// ---------------- kernel 1: zero the output ----------------------------------
__global__ void zero_kernel(float4* __restrict__ out, int n4) {
    int i = blockIdx.x * blockDim.x + threadIdx.x;
    int stride = gridDim.x * blockDim.x;
    float4 z = make_float4(0.f, 0.f, 0.f, 0.f);
    for (; i < n4; i += stride) out[i] = z;
}

// ---------------- kernel 2: fused softmax + (1 or 2) GEMMs -------------------
// Block = 256 threads (8 warps), 64 rows per block, warp -> 8 rows,
// thread -> cols [4*lane, 4*lane+4). W staged in 16-row K-chunks.
// Static SMEM: p 32KB + W chunks 16KB (NW=2) = 48KB.
template <int NW>
__global__ __launch_bounds__(256) void softmax_gemm_kernel(
    const float* __restrict__ logits, int nrows,
    int wi0, int wi1, int qi0, int qi1) {
    __shared__ float sh_p[64 * D];          // 32 KB, plain f32
    __shared__ float shW[NW][KC * D];       // 8 KB per W matrix

    const int tid  = threadIdx.x;
    const int lane = tid & 31;
    const int warp = tid >> 5;
    const int row0 = blockIdx.x * 64;

    // ---- softmax phase: each warp handles 8 rows; lane t owns cols t,t+32,t+64,t+96
    #pragma unroll
    for (int r = 0; r < 8; r++) {
        int lrow = warp * 8 + r;
        int row = row0 + lrow;
        float v[4];
        if (row < nrows) {
            const float* xr = logits + (size_t)row * D;
            #pragma unroll
            for (int j = 0; j < 4; j++) v[j] = xr[lane + 32 * j];
            float m = fmaxf(fmaxf(v[0], v[1]), fmaxf(v[2], v[3]));
            #pragma unroll
            for (int o = 16; o > 0; o >>= 1) m = fmaxf(m, __shfl_xor_sync(0xffffffffu, m, o));
            float s = 0.f;
            #pragma unroll
            for (int j = 0; j < 4; j++) { v[j] = expf(v[j] - m); s += v[j]; }
            #pragma unroll
            for (int o = 16; o > 0; o >>= 1) s += __shfl_xor_sync(0xffffffffu, s, o);
            float inv = 1.0f / s;
            #pragma unroll
            for (int j = 0; j < 4; j++) v[j] *= inv;
        } else {
            v[0] = v[1] = v[2] = v[3] = 0.f;
        }
        #pragma unroll
        for (int j = 0; j < 4; j++) sh_p[lrow * D + lane + 32 * j] = v[j];
    }

    // ---- GEMM phase: loop over 8 K-chunks of 16 rows each
    unsigned long long acc[NW][8][2];
    #pragma unroll
    for (int w = 0; w < NW; w++)
        #pragma unroll
        for (int r = 0; r < 8; r++) { acc[w][r][0] = 0ull; acc[w][r][1] = 0ull; }

    const int lrow0 = warp * 8;
    const float* p_base = sh_p + lrow0 * D;
    const int c0 = 4 * lane;

    for (int kc = 0; kc < D / KC; kc++) {
        __syncthreads();   // protect shW from previous iteration's readers
        // stage W chunk(s): KC*D floats = 512 float4 per W, 256 threads -> 2 each
        {
            const float4* s0 = (const float4*)(g_W[wi0] + kc * KC * D);
            float4* d0 = (float4*)shW[0];
            #pragma unroll
            for (int i = 0; i < KC * D / 4 / 256; i++) d0[tid + 256 * i] = s0[tid + 256 * i];
            if constexpr (NW == 2) {
                const float4* s1 = (const float4*)(g_W[wi1] + kc * KC * D);
                float4* d1 = (float4*)shW[1];
                #pragma unroll
                for (int i = 0; i < KC * D / 4 / 256; i++) d1[tid + 256 * i] = s1[tid + 256 * i];
            }
        }
        __syncthreads();

        const float* pk = p_base + kc * KC;
        #pragma unroll
        for (int kk = 0; kk < KC; kk++) {
            ulonglong2 w0 = *(const ulonglong2*)(shW[0] + kk * D + c0);   // LDS.128
            ulonglong2 w1;
            if constexpr (NW == 2) w1 = *(const ulonglong2*)(shW[1] + kk * D + c0);
            #pragma unroll
            for (int r = 0; r < 8; r++) {
                unsigned long long pp = dup2(pk[r * D + kk]);             // LDS.32 bcast + MOV
                acc[0][r][0] = ffma2(pp, w0.x, acc[0][r][0]);
                acc[0][r][1] = ffma2(pp, w0.y, acc[0][r][1]);
                if constexpr (NW == 2) {
                    acc[1][r][0] = ffma2(pp, w1.x, acc[1][r][0]);
                    acc[1][r][1] = ffma2(pp, w1.y, acc[1][r][1]);
                }
            }
        }
    }

    // ---- epilogue: STG.128, coalesced
    #pragma unroll
    for (int r = 0; r < 8; r++) {
        int row = row0 + lrow0 + r;
        if (row < nrows) {
            ulonglong2 o0; o0.x = acc[0][r][0]; o0.y = acc[0][r][1];
            *(ulonglong2*)(g_Q[qi0] + (size_t)row * D + c0) = o0;
            if constexpr (NW == 2) {
                ulonglong2 o1; o1.x = acc[1][r][0]; o1.y = acc[1][r][1];
                *(ulonglong2*)(g_Q[qi1] + (size_t)row * D + c0) = o1;
            }
        }
    }
}

// ---------------- kernel 3: edge scatter (gather Q row, vector-red into out) -
__global__ void scatter_kernel(const int* __restrict__ edges, int E, int qi,
                               float* __restrict__ out) {
    int gw   = (blockIdx.x * blockDim.x + threadIdx.x) >> 5;
    int lane = threadIdx.x & 31;
    int nw   = (gridDim.x * blockDim.x) >> 5;
    const float* Q = g_Q[qi];
    for (int e = gw; e < E; e += nw) {
        int s = edges[e];        // src
        int d = edges[E + e];    // dst
        float4 v = *(const float4*)(Q + (size_t)s * D + 4 * lane);
        float* p = out + (size_t)d * D + 4 * lane;
        asm volatile("red.global.add.v4.f32 [%0], {%1,%2,%3,%4};"
                     :: "l"(p), "f"(v.x), "f"(v.y), "f"(v.z), "f"(v.w)
                     : "memory");
    }
}

// ---------------- launch -----------------------------------------------------
extern "C" void kernel_launch(void* const* d_in, const int* in_sizes, int n_in,
                              void* d_out, int out_size) {
    const float* logits_A = (const float*)d_in[0];
    const float* logits_B = (const float*)d_in[1];
    // d_in[2], d_in[3] = frozen_A/frozen_B (unused by the math)
    const int* e_AB = (const int*)d_in[4];
    const int* e_BA = (const int*)d_in[5];
    const int* e_AA = (const int*)d_in[6];
    const float* Wp_AB = (const float*)d_in[7],  *Wn_AB = (const float*)d_in[8];
    const float* Wp_BA = (const float*)d_in[9],  *Wn_BA = (const float*)d_in[10];
    const float* Wp_AA = (const float*)d_in[11], *Wn_AA = (const float*)d_in[12];
    float* out = (float*)d_out;

    const int NA = in_sizes[0] / D;
    const int NB = in_sizes[1] / D;
    const int E_AB = in_sizes[4] / 2;
    const int E_BA = in_sizes[5] / 2;
    const int E_AA = in_sizes[6] / 2;

    // 0) fused W matrices
    compute_W_kernel<<<(3 * D * D + 255) / 256, 256>>>(Wp_AB, Wn_AB, Wp_BA, Wn_BA, Wp_AA, Wn_AA);

    // 1) zero output (out = [delta_A | delta_B])
    zero_kernel<<<2048, 256>>>((float4*)d_out, out_size / 4);

    // 2) Q_AB & Q_AA from logits_A (one pass), Q_BA from logits_B
    softmax_gemm_kernel<2><<<(NA + 63) / 64, 256>>>(logits_A, NA, 0, 2, 0, 2);
    softmax_gemm_kernel<1><<<(NB + 63) / 64, 256>>>(logits_B, NB, 1, -1, 1, -1);

    // 3) scatters: AB -> delta_B, BA -> delta_A, AA -> delta_A
    float* dA = out;
    float* dB = out + (size_t)NA * D;
    scatter_kernel<<<2048, 256>>>(e_AB, E_AB, 0, dB);
    scatter_kernel<<<2048, 256>>>(e_BA, E_BA, 1, dA);
    scatter_kernel<<<2048, 256>>>(e_AA, E_AA, 2, dA);
}

// round 4
// speedup vs baseline: 1.2618x; 1.2618x over previous
#include <cuda_runtime.h>
#include <cuda_bf16.h>
#include <cstdint>

#define D 128
#define MAXN 100000

// ---------------- device scratch (allocation-free) ---------------------------
// g_Wfrag[type][kstep(8)][ntile(16)][lane(32)] : uint4 = {b0_hi, b1_hi, b0_lo, b1_lo}
// packed exactly in mma.m16n8k16 col-major B fragment order.
__device__ __align__(16) uint4 g_Wfrag[3][8][16][32];
__device__ float g_Q[3][(size_t)MAXN * D];

// ---------------- mma.sync helper (sm_80+ path, legal on target sm_103) ------
__device__ __forceinline__ void mma_bf16(float* c, uint32_t a0, uint32_t a1,
                                         uint32_t a2, uint32_t a3,
                                         uint32_t b0, uint32_t b1) {
    asm volatile(
        "mma.sync.aligned.m16n8k16.row.col.f32.bf16.bf16.f32 "
        "{%0,%1,%2,%3}, {%4,%5,%6,%7}, {%8,%9}, {%0,%1,%2,%3};"
        : "+f"(c[0]), "+f"(c[1]), "+f"(c[2]), "+f"(c[3])
        : "r"(a0), "r"(a1), "r"(a2), "r"(a3), "r"(b0), "r"(b1));
}

// ---------------- kernel 0: W = W_pos - softplus(W_negraw), split + frag-pack -
__global__ void compute_W_kernel(const float* __restrict__ wp0, const float* __restrict__ wn0,
                                 const float* __restrict__ wp1, const float* __restrict__ wn1,
                                 const float* __restrict__ wp2, const float* __restrict__ wn2) {
    int i = blockIdx.x * blockDim.x + threadIdx.x;
    if (i >= 3 * D * D) return;
    int ty = i / (D * D), r = i % (D * D);
    int k = r / D, n = r % D;
    const float* wp = (ty == 0) ? wp0 : (ty == 1 ? wp1 : wp2);
    const float* wn = (ty == 0) ? wn0 : (ty == 1 ? wn1 : wn2);
    float x = wn[r];
    float sp = fmaxf(x, 0.0f) + log1pf(expf(-fabsf(x)));
    float w = wp[r] - sp;
    __nv_bfloat16 hb = __float2bfloat16(w);
    __nv_bfloat16 lb = __float2bfloat16(w - __bfloat162float(hb));

    // B fragment coords for mma m16n8k16 col-major:
    // lane = g*4 + tq with g = n&7; b0 holds k = 16s + 2tq (+1), b1 holds +8.
    int s  = k >> 4;
    int kk = k & 15;
    int reg  = kk >> 3;             // 0 -> b0, 1 -> b1
    int tq   = (kk >> 1) & 3;
    int half = kk & 1;
    int j    = n >> 3;
    int lane = (n & 7) * 4 + tq;

    unsigned char* slot = (unsigned char*)&g_Wfrag[ty][s][j][lane];
    *(__nv_bfloat16*)(slot + 0 + reg * 4 + half * 2) = hb;   // hi split
    *(__nv_bfloat16*)(slot + 8 + reg * 4 + half * 2) = lb;   // lo split
}

// ---------------- kernel 1: zero output --------------------------------------
__global__ void zero_kernel(float4* __restrict__ out, int n4) {
    int i = blockIdx.x * blockDim.x + threadIdx.x;
    int stride = gridDim.x * blockDim.x;
    float4 z = make_float4(0.f, 0.f, 0.f, 0.f);
    for (; i < n4; i += stride) out[i] = z;
}

// ---------------- kernel 2: fused softmax + split-bf16 HMMA GEMM -------------
// block = 128 threads (4 warps), 64 rows/CTA, warp -> 16 rows (one M16 tile).
// smem: p hi/lo as [64][136] bf16 (pad 8 -> conflict-free A-fragment loads).
#define PROW 136   // padded row length in bf16 elements (68 words)

__global__ void __launch_bounds__(128)
hmma_gemm_kernel(const float* __restrict__ X, int nrows, int type) {
    __shared__ __align__(16) __nv_bfloat16 sph[64 * PROW];
    __shared__ __align__(16) __nv_bfloat16 spl[64 * PROW];

    const int tid  = threadIdx.x;
    const int lane = tid & 31;
    const int warp = tid >> 5;
    const int row0 = blockIdx.x * 64;

    // ---- softmax: warp handles rows [warp*16, warp*16+16); lane owns 4 cols
    for (int r = 0; r < 16; r++) {
        int lrow = warp * 16 + r;
        int row  = row0 + lrow;
        if (row < nrows) {
            const float* xr = X + (size_t)row * D;
            float v[4];
            #pragma unroll
            for (int q = 0; q < 4; q++) v[q] = xr[lane + 32 * q];
            float m = fmaxf(fmaxf(v[0], v[1]), fmaxf(v[2], v[3]));
            #pragma unroll
            for (int o = 16; o > 0; o >>= 1) m = fmaxf(m, __shfl_xor_sync(0xffffffffu, m, o));
            float s = 0.f;
            #pragma unroll
            for (int q = 0; q < 4; q++) { v[q] = expf(v[q] - m); s += v[q]; }
            #pragma unroll
            for (int o = 16; o > 0; o >>= 1) s += __shfl_xor_sync(0xffffffffu, s, o);
            float inv = 1.0f / s;
            #pragma unroll
            for (int q = 0; q < 4; q++) {
                float p = v[q] * inv;
                __nv_bfloat16 hb = __float2bfloat16(p);
                __nv_bfloat16 lb = __float2bfloat16(p - __bfloat162float(hb));
                int col = lane + 32 * q;
                sph[lrow * PROW + col] = hb;
                spl[lrow * PROW + col] = lb;
            }
        } else {
            __nv_bfloat16 z = __float2bfloat16(0.f);
            #pragma unroll
            for (int q = 0; q < 4; q++) {
                int col = lane + 32 * q;
                sph[lrow * PROW + col] = z;
                spl[lrow * PROW + col] = z;
            }
        }
    }
    __syncthreads();

    // ---- HMMA mainloop
    const int g  = lane >> 2;     // row within M16 tile (and +8)
    const int tq = lane & 3;

    float acc[64];
    #pragma unroll
    for (int i = 0; i < 64; i++) acc[i] = 0.f;

    const uint32_t* ph32 = (const uint32_t*)sph;
    const uint32_t* pl32 = (const uint32_t*)spl;
    const int rbase = (warp * 16 + g) * (PROW / 2);     // u32 row index
    const uint4* wf = &g_Wfrag[type][0][0][0];

    for (int s = 0; s < 8; s++) {
        const int o = rbase + 8 * s + tq;
        uint32_t ah0 = ph32[o],            ah2 = ph32[o + 4];
        uint32_t ah1 = ph32[o + 8 * 68],   ah3 = ph32[o + 4 + 8 * 68];
        uint32_t al0 = pl32[o],            al2 = pl32[o + 4];
        uint32_t al1 = pl32[o + 8 * 68],   al3 = pl32[o + 4 + 8 * 68];
        const uint4* wfs = wf + (s * 16) * 32 + lane;
        #pragma unroll
        for (int j = 0; j < 16; j++) {
            uint4 b = wfs[j * 32];
            mma_bf16(acc + 4 * j, ah0, ah1, ah2, ah3, b.x, b.y);   // Ph @ Wh
            mma_bf16(acc + 4 * j, al0, al1, al2, al3, b.x, b.y);   // Pl @ Wh
            mma_bf16(acc + 4 * j, ah0, ah1, ah2, ah3, b.z, b.w);   // Ph @ Wl
        }
    }

    // ---- epilogue: acc -> Q (STG.64)
    float* Q = g_Q[type];
    const int rowa = row0 + warp * 16 + g;
    const int rowb = rowa + 8;
    #pragma unroll
    for (int j = 0; j < 16; j++) {
        int cn = 8 * j + 2 * tq;
        if (rowa < nrows)
            *(float2*)(Q + (size_t)rowa * D + cn) = make_float2(acc[4 * j], acc[4 * j + 1]);
        if (rowb < nrows)
            *(float2*)(Q + (size_t)rowb * D + cn) = make_float2(acc[4 * j + 2], acc[4 * j + 3]);
    }
}

// ---------------- kernel 3: merged edge scatter ------------------------------
__global__ void scatter_kernel(const int* __restrict__ e0, int E0,
                               const int* __restrict__ e1, int E1,
                               const int* __restrict__ e2, int E2,
                               float* __restrict__ dA, float* __restrict__ dB) {
    int gw   = (blockIdx.x * blockDim.x + threadIdx.x) >> 5;
    int lane = threadIdx.x & 31;
    int nw   = (gridDim.x * blockDim.x) >> 5;
    int ET = E0 + E1 + E2;
    for (int e = gw; e < ET; e += nw) {
        const int* eb; int le, Ecur; const float* Q; float* out;
        if (e < E0)            { eb = e0; le = e;            Ecur = E0; Q = g_Q[0]; out = dB; }
        else if (e < E0 + E1)  { eb = e1; le = e - E0;       Ecur = E1; Q = g_Q[1]; out = dA; }
        else                   { eb = e2; le = e - E0 - E1;  Ecur = E2; Q = g_Q[2]; out = dA; }
        int sidx = eb[le];
        int didx = eb[Ecur + le];
        float4 v = *(const float4*)(Q + (size_t)sidx * D + 4 * lane);
        float* p = out + (size_t)didx * D + 4 * lane;
        asm volatile("red.global.add.v4.f32 [%0], {%1,%2,%3,%4};"
                     :: "l"(p), "f"(v.x), "f"(v.y), "f"(v.z), "f"(v.w) : "memory");
    }
}

// ---------------- launch -----------------------------------------------------
extern "C" void kernel_launch(void* const* d_in, const int* in_sizes, int n_in,
                              void* d_out, int out_size) {
    const float* logits_A = (const float*)d_in[0];
    const float* logits_B = (const float*)d_in[1];
    const int* e_AB = (const int*)d_in[4];
    const int* e_BA = (const int*)d_in[5];
    const int* e_AA = (const int*)d_in[6];
    const float* Wp_AB = (const float*)d_in[7],  *Wn_AB = (const float*)d_in[8];
    const float* Wp_BA = (const float*)d_in[9],  *Wn_BA = (const float*)d_in[10];
    const float* Wp_AA = (const float*)d_in[11], *Wn_AA = (const float*)d_in[12];
    float* out = (float*)d_out;

    const int NA = in_sizes[0] / D;
    const int NB = in_sizes[1] / D;
    const int E_AB = in_sizes[4] / 2;
    const int E_BA = in_sizes[5] / 2;
    const int E_AA = in_sizes[6] / 2;

    compute_W_kernel<<<(3 * D * D + 255) / 256, 256>>>(Wp_AB, Wn_AB, Wp_BA, Wn_BA, Wp_AA, Wn_AA);
    zero_kernel<<<2048, 256>>>((float4*)d_out, out_size / 4);

    hmma_gemm_kernel<<<(NA + 63) / 64, 128>>>(logits_A, NA, 0);
    hmma_gemm_kernel<<<(NB + 63) / 64, 128>>>(logits_B, NB, 1);
    hmma_gemm_kernel<<<(NA + 63) / 64, 128>>>(logits_A, NA, 2);

    float* dA = out;
    float* dB = out + (size_t)NA * D;
    scatter_kernel<<<2048, 256>>>(e_AB, E_AB, e_BA, E_BA, e_AA, E_AA, dA, dB);
}

// round 5
// speedup vs baseline: 1.4646x; 1.1607x over previous
#include <cuda_runtime.h>
#include <cuda_bf16.h>
#include <cstdint>

#define D 128
#define MAXN 100000

// ---------------- device scratch (allocation-free) ---------------------------
// g_Wfrag[type][kstep(8)][ntile(16)][lane(32)] : uint4 = {b0_hi, b1_hi, b0_lo, b1_lo}
// packed exactly in mma.m16n8k16 col-major B fragment order.
__device__ __align__(16) uint4 g_Wfrag[3][8][16][32];
__device__ float g_Q[3][(size_t)MAXN * D];

// ---------------- mma.sync helper (sm_80+ path, legal on target sm_103) ------
__device__ __forceinline__ void mma_bf16(float* c, uint32_t a0, uint32_t a1,
                                         uint32_t a2, uint32_t a3,
                                         uint32_t b0, uint32_t b1) {
    asm volatile(
        "mma.sync.aligned.m16n8k16.row.col.f32.bf16.bf16.f32 "
        "{%0,%1,%2,%3}, {%4,%5,%6,%7}, {%8,%9}, {%0,%1,%2,%3};"
        : "+f"(c[0]), "+f"(c[1]), "+f"(c[2]), "+f"(c[3])
        : "r"(a0), "r"(a1), "r"(a2), "r"(a3), "r"(b0), "r"(b1));
}

// ---------------- kernel 0: W = W_pos - softplus(W_negraw), split + frag-pack -
__global__ void compute_W_kernel(const float* __restrict__ wp0, const float* __restrict__ wn0,
                                 const float* __restrict__ wp1, const float* __restrict__ wn1,
                                 const float* __restrict__ wp2, const float* __restrict__ wn2) {
    int i = blockIdx.x * blockDim.x + threadIdx.x;
    if (i >= 3 * D * D) return;
    int ty = i / (D * D), r = i % (D * D);
    int k = r / D, n = r % D;
    const float* wp = (ty == 0) ? wp0 : (ty == 1 ? wp1 : wp2);
    const float* wn = (ty == 0) ? wn0 : (ty == 1 ? wn1 : wn2);
    float x = wn[r];
    float sp = fmaxf(x, 0.0f) + log1pf(expf(-fabsf(x)));
    float w = wp[r] - sp;
    __nv_bfloat16 hb = __float2bfloat16(w);
    __nv_bfloat16 lb = __float2bfloat16(w - __bfloat162float(hb));

    // B fragment coords for mma m16n8k16 col-major:
    // lane = g*4 + tq with g = n&7; b0 holds k = 16s + 2tq (+1), b1 holds +8.
    int s  = k >> 4;
    int kk = k & 15;
    int reg  = kk >> 3;             // 0 -> b0, 1 -> b1
    int tq   = (kk >> 1) & 3;
    int half = kk & 1;
    int j    = n >> 3;
    int lane = (n & 7) * 4 + tq;

    unsigned char* slot = (unsigned char*)&g_Wfrag[ty][s][j][lane];
    *(__nv_bfloat16*)(slot + 0 + reg * 4 + half * 2) = hb;   // hi split
    *(__nv_bfloat16*)(slot + 8 + reg * 4 + half * 2) = lb;   // lo split
}

// ---------------- kernel 1: zero output --------------------------------------
__global__ void zero_kernel(float4* __restrict__ out, int n4) {
    int i = blockIdx.x * blockDim.x + threadIdx.x;
    int stride = gridDim.x * blockDim.x;
    float4 z = make_float4(0.f, 0.f, 0.f, 0.f);
    for (; i < n4; i += stride) out[i] = z;
}

// ---------------- kernel 2: fused softmax + split-bf16 HMMA GEMM -------------
// Block = 256 threads (8 warps), 64 rows/CTA.
// Warp -> (mtile = wid>>1, N-half = wid&1): acc = 32 floats, ~80 regs ->
// 3 CTAs/SM = 24 warps/SM. Types t0 (and t1 if >=0) computed in one pass,
// sharing the softmax'd P tile in smem.
#define PROW 136   // padded row length in bf16 elements (68 u32 words)

__global__ void __launch_bounds__(256)
hmma_gemm_kernel(const float* __restrict__ X, int nrows, int t0, int t1) {
    __shared__ __align__(16) __nv_bfloat16 sph[64 * PROW];
    __shared__ __align__(16) __nv_bfloat16 spl[64 * PROW];

    const int tid  = threadIdx.x;
    const int lane = tid & 31;
    const int warp = tid >> 5;
    const int row0 = blockIdx.x * 64;

    // ---- softmax: 8 warps x 8 rows each; lane owns 4 cols of its row
    #pragma unroll
    for (int r = 0; r < 8; r++) {
        int lrow = warp * 8 + r;
        int row  = row0 + lrow;
        if (row < nrows) {
            const float* xr = X + (size_t)row * D;
            float v[4];
            #pragma unroll
            for (int q = 0; q < 4; q++) v[q] = xr[lane + 32 * q];
            float m = fmaxf(fmaxf(v[0], v[1]), fmaxf(v[2], v[3]));
            #pragma unroll
            for (int o = 16; o > 0; o >>= 1) m = fmaxf(m, __shfl_xor_sync(0xffffffffu, m, o));
            float s = 0.f;
            #pragma unroll
            for (int q = 0; q < 4; q++) { v[q] = expf(v[q] - m); s += v[q]; }
            #pragma unroll
            for (int o = 16; o > 0; o >>= 1) s += __shfl_xor_sync(0xffffffffu, s, o);
            float inv = 1.0f / s;
            #pragma unroll
            for (int q = 0; q < 4; q++) {
                float p = v[q] * inv;
                __nv_bfloat16 hb = __float2bfloat16(p);
                __nv_bfloat16 lb = __float2bfloat16(p - __bfloat162float(hb));
                int col = lane + 32 * q;
                sph[lrow * PROW + col] = hb;
                spl[lrow * PROW + col] = lb;
            }
        } else {
            __nv_bfloat16 z = __float2bfloat16(0.f);
            #pragma unroll
            for (int q = 0; q < 4; q++) {
                int col = lane + 32 * q;
                sph[lrow * PROW + col] = z;
                spl[lrow * PROW + col] = z;
            }
        }
    }
    __syncthreads();

    // ---- warp tiling: mtile (16 rows) x N-half (64 cols = 8 ntiles)
    const int mt = warp >> 1;          // 0..3
    const int nh = warp & 1;           // 0..1
    const int g  = lane >> 2;
    const int tq = lane & 3;

    const uint32_t* ph32 = (const uint32_t*)sph;
    const uint32_t* pl32 = (const uint32_t*)spl;
    const int rbase = (mt * 16 + g) * (PROW / 2);

    const int ntypes = (t1 >= 0) ? 2 : 1;
    for (int tt = 0; tt < ntypes; tt++) {
        const int ty = tt ? t1 : t0;
        const uint4* wf = &g_Wfrag[ty][0][8 * nh][0];

        float acc[32];
        #pragma unroll
        for (int i = 0; i < 32; i++) acc[i] = 0.f;

        #pragma unroll
        for (int s = 0; s < 8; s++) {
            const int o = rbase + 8 * s + tq;
            uint32_t ah0 = ph32[o],           ah2 = ph32[o + 4];
            uint32_t ah1 = ph32[o + 8 * 68],  ah3 = ph32[o + 4 + 8 * 68];
            uint32_t al0 = pl32[o],           al2 = pl32[o + 4];
            uint32_t al1 = pl32[o + 8 * 68],  al3 = pl32[o + 4 + 8 * 68];
            const uint4* wfs = wf + (s * 16) * 32 + lane;
            #pragma unroll
            for (int j = 0; j < 8; j++) {
                uint4 b = wfs[j * 32];
                mma_bf16(acc + 4 * j, ah0, ah1, ah2, ah3, b.x, b.y);   // Ph @ Wh
                mma_bf16(acc + 4 * j, al0, al1, al2, al3, b.x, b.y);   // Pl @ Wh
                mma_bf16(acc + 4 * j, ah0, ah1, ah2, ah3, b.z, b.w);   // Ph @ Wl
            }
        }

        // ---- epilogue: acc -> Q[ty], cols [64*nh, 64*nh+64)
        float* Q = g_Q[ty];
        const int rowa = row0 + mt * 16 + g;
        const int rowb = rowa + 8;
        #pragma unroll
        for (int j = 0; j < 8; j++) {
            int cn = 64 * nh + 8 * j + 2 * tq;
            if (rowa < nrows)
                *(float2*)(Q + (size_t)rowa * D + cn) = make_float2(acc[4 * j], acc[4 * j + 1]);
            if (rowb < nrows)
                *(float2*)(Q + (size_t)rowb * D + cn) = make_float2(acc[4 * j + 2], acc[4 * j + 3]);
        }
    }
}

// ---------------- kernel 3: merged edge scatter ------------------------------
__global__ void scatter_kernel(const int* __restrict__ e0, int E0,
                               const int* __restrict__ e1, int E1,
                               const int* __restrict__ e2, int E2,
                               float* __restrict__ dA, float* __restrict__ dB) {
    int gw   = (blockIdx.x * blockDim.x + threadIdx.x) >> 5;
    int lane = threadIdx.x & 31;
    int nw   = (gridDim.x * blockDim.x) >> 5;
    int ET = E0 + E1 + E2;
    for (int e = gw; e < ET; e += nw) {
        const int* eb; int le, Ecur; const float* Q; float* out;
        if (e < E0)            { eb = e0; le = e;            Ecur = E0; Q = g_Q[0]; out = dB; }
        else if (e < E0 + E1)  { eb = e1; le = e - E0;       Ecur = E1; Q = g_Q[1]; out = dA; }
        else                   { eb = e2; le = e - E0 - E1;  Ecur = E2; Q = g_Q[2]; out = dA; }
        int sidx = eb[le];
        int didx = eb[Ecur + le];
        float4 v = *(const float4*)(Q + (size_t)sidx * D + 4 * lane);
        float* p = out + (size_t)didx * D + 4 * lane;
        asm volatile("red.global.add.v4.f32 [%0], {%1,%2,%3,%4};"
                     :: "l"(p), "f"(v.x), "f"(v.y), "f"(v.z), "f"(v.w) : "memory");
    }
}

// ---------------- launch -----------------------------------------------------
extern "C" void kernel_launch(void* const* d_in, const int* in_sizes, int n_in,
                              void* d_out, int out_size) {
    const float* logits_A = (const float*)d_in[0];
    const float* logits_B = (const float*)d_in[1];
    const int* e_AB = (const int*)d_in[4];
    const int* e_BA = (const int*)d_in[5];
    const int* e_AA = (const int*)d_in[6];
    const float* Wp_AB = (const float*)d_in[7],  *Wn_AB = (const float*)d_in[8];
    const float* Wp_BA = (const float*)d_in[9],  *Wn_BA = (const float*)d_in[10];
    const float* Wp_AA = (const float*)d_in[11], *Wn_AA = (const float*)d_in[12];
    float* out = (float*)d_out;

    const int NA = in_sizes[0] / D;
    const int NB = in_sizes[1] / D;
    const int E_AB = in_sizes[4] / 2;
    const int E_BA = in_sizes[5] / 2;
    const int E_AA = in_sizes[6] / 2;

    compute_W_kernel<<<(3 * D * D + 255) / 256, 256>>>(Wp_AB, Wn_AB, Wp_BA, Wn_BA, Wp_AA, Wn_AA);
    zero_kernel<<<2048, 256>>>((float4*)d_out, out_size / 4);

    // types 0 (AB) and 2 (AA) share softmax(logits_A) -> one fused kernel
    hmma_gemm_kernel<<<(NA + 63) / 64, 256>>>(logits_A, NA, 0, 2);
    hmma_gemm_kernel<<<(NB + 63) / 64, 256>>>(logits_B, NB, 1, -1);

    float* dA = out;
    float* dB = out + (size_t)NA * D;
    scatter_kernel<<<2048, 256>>>(e_AB, E_AB, e_BA, E_BA, e_AA, E_AA, dA, dB);
}

// round 6
// speedup vs baseline: 1.7881x; 1.2209x over previous
#include <cuda_runtime.h>
#include <cuda_bf16.h>
#include <cstdint>

#define D 128
#define MAXN 100000
#define CAP 64          // bucket capacity per destination (Poisson(10): P(>=64) ~ 1e-18)
#define NDST_MAX 200000

// ---------------- device scratch (allocation-free) ---------------------------
// g_Wfrag[type][kstep(8)][ntile(16)][lane(32)] : uint4 = {b0_hi, b1_hi, b0_lo, b1_lo}
__device__ __align__(16) uint4 g_Wfrag[3][8][16][32];
__device__ float g_Q[3][(size_t)MAXN * D];
__device__ int g_cnt[NDST_MAX];
__device__ unsigned g_bkt[(size_t)NDST_MAX * CAP];

// ---------------- mma.sync helper (sm_80+ path, legal on target sm_103) ------
__device__ __forceinline__ void mma_bf16(float* c, uint32_t a0, uint32_t a1,
                                         uint32_t a2, uint32_t a3,
                                         uint32_t b0, uint32_t b1) {
    asm volatile(
        "mma.sync.aligned.m16n8k16.row.col.f32.bf16.bf16.f32 "
        "{%0,%1,%2,%3}, {%4,%5,%6,%7}, {%8,%9}, {%0,%1,%2,%3};"
        : "+f"(c[0]), "+f"(c[1]), "+f"(c[2]), "+f"(c[3])
        : "r"(a0), "r"(a1), "r"(a2), "r"(a3), "r"(b0), "r"(b1));
}

// ---------------- kernel 0: W = W_pos - softplus(W_negraw), split + frag-pack -
__global__ void compute_W_kernel(const float* __restrict__ wp0, const float* __restrict__ wn0,
                                 const float* __restrict__ wp1, const float* __restrict__ wn1,
                                 const float* __restrict__ wp2, const float* __restrict__ wn2) {
    int i = blockIdx.x * blockDim.x + threadIdx.x;
    if (i >= 3 * D * D) return;
    int ty = i / (D * D), r = i % (D * D);
    int k = r / D, n = r % D;
    const float* wp = (ty == 0) ? wp0 : (ty == 1 ? wp1 : wp2);
    const float* wn = (ty == 0) ? wn0 : (ty == 1 ? wn1 : wn2);
    float x = wn[r];
    float sp = fmaxf(x, 0.0f) + log1pf(expf(-fabsf(x)));
    float w = wp[r] - sp;
    __nv_bfloat16 hb = __float2bfloat16(w);
    __nv_bfloat16 lb = __float2bfloat16(w - __bfloat162float(hb));

    int s  = k >> 4;
    int kk = k & 15;
    int reg  = kk >> 3;
    int tq   = (kk >> 1) & 3;
    int half = kk & 1;
    int j    = n >> 3;
    int lane = (n & 7) * 4 + tq;

    unsigned char* slot = (unsigned char*)&g_Wfrag[ty][s][j][lane];
    *(__nv_bfloat16*)(slot + 0 + reg * 4 + half * 2) = hb;
    *(__nv_bfloat16*)(slot + 8 + reg * 4 + half * 2) = lb;
}

// ---------------- kernel 1: zero destination counts --------------------------
__global__ void zero_cnt_kernel(int ndst) {
    int i = blockIdx.x * blockDim.x + threadIdx.x;
    if (i < ndst) g_cnt[i] = 0;
}

// ---------------- kernel 2: fused softmax + split-bf16 HMMA GEMM -------------
#define PROW 136

__global__ void __launch_bounds__(256)
hmma_gemm_kernel(const float* __restrict__ X, int nrows, int t0, int t1) {
    __shared__ __align__(16) __nv_bfloat16 sph[64 * PROW];
    __shared__ __align__(16) __nv_bfloat16 spl[64 * PROW];

    const int tid  = threadIdx.x;
    const int lane = tid & 31;
    const int warp = tid >> 5;
    const int row0 = blockIdx.x * 64;

    #pragma unroll
    for (int r = 0; r < 8; r++) {
        int lrow = warp * 8 + r;
        int row  = row0 + lrow;
        if (row < nrows) {
            const float* xr = X + (size_t)row * D;
            float v[4];
            #pragma unroll
            for (int q = 0; q < 4; q++) v[q] = xr[lane + 32 * q];
            float m = fmaxf(fmaxf(v[0], v[1]), fmaxf(v[2], v[3]));
            #pragma unroll
            for (int o = 16; o > 0; o >>= 1) m = fmaxf(m, __shfl_xor_sync(0xffffffffu, m, o));
            float s = 0.f;
            #pragma unroll
            for (int q = 0; q < 4; q++) { v[q] = expf(v[q] - m); s += v[q]; }
            #pragma unroll
            for (int o = 16; o > 0; o >>= 1) s += __shfl_xor_sync(0xffffffffu, s, o);
            float inv = 1.0f / s;
            #pragma unroll
            for (int q = 0; q < 4; q++) {
                float p = v[q] * inv;
                __nv_bfloat16 hb = __float2bfloat16(p);
                __nv_bfloat16 lb = __float2bfloat16(p - __bfloat162float(hb));
                int col = lane + 32 * q;
                sph[lrow * PROW + col] = hb;
                spl[lrow * PROW + col] = lb;
            }
        } else {
            __nv_bfloat16 z = __float2bfloat16(0.f);
            #pragma unroll
            for (int q = 0; q < 4; q++) {
                int col = lane + 32 * q;
                sph[lrow * PROW + col] = z;
                spl[lrow * PROW + col] = z;
            }
        }
    }
    __syncthreads();

    const int mt = warp >> 1;
    const int nh = warp & 1;
    const int g  = lane >> 2;
    const int tq = lane & 3;

    const uint32_t* ph32 = (const uint32_t*)sph;
    const uint32_t* pl32 = (const uint32_t*)spl;
    const int rbase = (mt * 16 + g) * (PROW / 2);

    const int ntypes = (t1 >= 0) ? 2 : 1;
    for (int tt = 0; tt < ntypes; tt++) {
        const int ty = tt ? t1 : t0;
        const uint4* wf = &g_Wfrag[ty][0][8 * nh][0];

        float acc[32];
        #pragma unroll
        for (int i = 0; i < 32; i++) acc[i] = 0.f;

        #pragma unroll
        for (int s = 0; s < 8; s++) {
            const int o = rbase + 8 * s + tq;
            uint32_t ah0 = ph32[o],           ah2 = ph32[o + 4];
            uint32_t ah1 = ph32[o + 8 * 68],  ah3 = ph32[o + 4 + 8 * 68];
            uint32_t al0 = pl32[o],           al2 = pl32[o + 4];
            uint32_t al1 = pl32[o + 8 * 68],  al3 = pl32[o + 4 + 8 * 68];
            const uint4* wfs = wf + (s * 16) * 32 + lane;
            #pragma unroll
            for (int j = 0; j < 8; j++) {
                uint4 b = wfs[j * 32];
                mma_bf16(acc + 4 * j, ah0, ah1, ah2, ah3, b.x, b.y);
                mma_bf16(acc + 4 * j, al0, al1, al2, al3, b.x, b.y);
                mma_bf16(acc + 4 * j, ah0, ah1, ah2, ah3, b.z, b.w);
            }
        }

        float* Q = g_Q[ty];
        const int rowa = row0 + mt * 16 + g;
        const int rowb = rowa + 8;
        #pragma unroll
        for (int j = 0; j < 8; j++) {
            int cn = 64 * nh + 8 * j + 2 * tq;
            if (rowa < nrows)
                *(float2*)(Q + (size_t)rowa * D + cn) = make_float2(acc[4 * j], acc[4 * j + 1]);
            if (rowb < nrows)
                *(float2*)(Q + (size_t)rowb * D + cn) = make_float2(acc[4 * j + 2], acc[4 * j + 3]);
        }
    }
}

// ---------------- kernel 3: edge placement into per-dst buckets --------------
// slot value: src | (q << 20)  (src < 2^20, q in {0,1,2})
// global dst: A rows [0,NA), B rows [NA, NA+NB)
__global__ void place_kernel(const int* __restrict__ e0, int E0,   // AB: dst B, Q0
                             const int* __restrict__ e1, int E1,   // BA: dst A, Q1
                             const int* __restrict__ e2, int E2,   // AA: dst A, Q2
                             int NA) {
    int i = blockIdx.x * blockDim.x + threadIdx.x;
    int stride = gridDim.x * blockDim.x;
    int ET = E0 + E1 + E2;
    for (int e = i; e < ET; e += stride) {
        int src, gdst; unsigned q;
        if (e < E0)            { src = e0[e];           gdst = NA + e0[E0 + e];      q = 0; }
        else if (e < E0 + E1)  { int le = e - E0;       src = e1[le]; gdst = e1[E1 + le]; q = 1; }
        else                   { int le = e - E0 - E1;  src = e2[le]; gdst = e2[E2 + le]; q = 2; }
        int pos = atomicAdd(&g_cnt[gdst], 1);
        if (pos < CAP) g_bkt[(size_t)gdst * CAP + pos] = (unsigned)src | (q << 20);
    }
}

// ---------------- kernel 4: per-dst gather + register accumulate -------------
// warp per destination row; writes every output row exactly once (no atomics,
// and no separate zero pass needed).
__global__ void __launch_bounds__(256)
gather_kernel(float* __restrict__ out, int ndst) {
    int gw   = (blockIdx.x * blockDim.x + threadIdx.x) >> 5;
    int lane = threadIdx.x & 31;
    if (gw >= ndst) return;

    int cnt = g_cnt[gw];
    cnt = min(cnt, CAP);
    const unsigned* bk = g_bkt + (size_t)gw * CAP;
    const float* Qf = &g_Q[0][0];

    float4 acc = make_float4(0.f, 0.f, 0.f, 0.f);

    int n1 = min(cnt, 32);
    unsigned pk = (lane < n1) ? bk[lane] : 0u;
    for (int e = 0; e < n1; e++) {
        unsigned p = __shfl_sync(0xffffffffu, pk, e);
        const float* Qr = Qf + (size_t)(p >> 20) * ((size_t)MAXN * D) + (size_t)(p & 0xFFFFFu) * D;
        float4 v = *(const float4*)(Qr + 4 * lane);
        acc.x += v.x; acc.y += v.y; acc.z += v.z; acc.w += v.w;
    }
    if (cnt > 32) {
        int n2 = cnt - 32;
        unsigned pk2 = (lane < n2) ? bk[32 + lane] : 0u;
        for (int e = 0; e < n2; e++) {
            unsigned p = __shfl_sync(0xffffffffu, pk2, e);
            const float* Qr = Qf + (size_t)(p >> 20) * ((size_t)MAXN * D) + (size_t)(p & 0xFFFFFu) * D;
            float4 v = *(const float4*)(Qr + 4 * lane);
            acc.x += v.x; acc.y += v.y; acc.z += v.z; acc.w += v.w;
        }
    }

    *(float4*)(out + (size_t)gw * D + 4 * lane) = acc;
}

// ---------------- launch -----------------------------------------------------
extern "C" void kernel_launch(void* const* d_in, const int* in_sizes, int n_in,
                              void* d_out, int out_size) {
    const float* logits_A = (const float*)d_in[0];
    const float* logits_B = (const float*)d_in[1];
    const int* e_AB = (const int*)d_in[4];
    const int* e_BA = (const int*)d_in[5];
    const int* e_AA = (const int*)d_in[6];
    const float* Wp_AB = (const float*)d_in[7],  *Wn_AB = (const float*)d_in[8];
    const float* Wp_BA = (const float*)d_in[9],  *Wn_BA = (const float*)d_in[10];
    const float* Wp_AA = (const float*)d_in[11], *Wn_AA = (const float*)d_in[12];
    float* out = (float*)d_out;

    const int NA = in_sizes[0] / D;
    const int NB = in_sizes[1] / D;
    const int E_AB = in_sizes[4] / 2;
    const int E_BA = in_sizes[5] / 2;
    const int E_AA = in_sizes[6] / 2;
    const int NDST = NA + NB;
    const int ET = E_AB + E_BA + E_AA;

    compute_W_kernel<<<(3 * D * D + 255) / 256, 256>>>(Wp_AB, Wn_AB, Wp_BA, Wn_BA, Wp_AA, Wn_AA);
    zero_cnt_kernel<<<(NDST + 255) / 256, 256>>>(NDST);
    place_kernel<<<min((ET + 255) / 256, 8192), 256>>>(e_AB, E_AB, e_BA, E_BA, e_AA, E_AA, NA);

    // types 0 (AB) and 2 (AA) share softmax(logits_A) -> one fused kernel
    hmma_gemm_kernel<<<(NA + 63) / 64, 256>>>(logits_A, NA, 0, 2);
    hmma_gemm_kernel<<<(NB + 63) / 64, 256>>>(logits_B, NB, 1, -1);

    // out = [delta_A | delta_B]; global dst indexing matches out rows directly
    gather_kernel<<<(NDST * 32 + 255) / 256, 256>>>(out, NDST);
}

// round 9
// speedup vs baseline: 1.8550x; 1.0374x over previous
#include <cuda_runtime.h>
#include <cuda_bf16.h>
#include <cstdint>

#define D 128
#define MAXN 100000
#define CAP 64          // bucket capacity per destination (Poisson(10): P(>=64) ~ 1e-18)
#define NDST_MAX 200000

// ---------------- device scratch (allocation-free) ---------------------------
// g_Wfrag[type][kstep(8)][ntile(16)][lane(32)] : uint4 = {b0_hi, b1_hi, b0_lo, b1_lo}
__device__ __align__(16) uint4 g_Wfrag[3][8][16][32];
__device__ float g_Q[3][(size_t)MAXN * D];
__device__ int g_cnt[NDST_MAX];
__device__ unsigned g_bkt[(size_t)NDST_MAX * CAP];

// ---------------- mma.sync helper (sm_80+ path, legal on target sm_103) ------
__device__ __forceinline__ void mma_bf16(float* c, uint32_t a0, uint32_t a1,
                                         uint32_t a2, uint32_t a3,
                                         uint32_t b0, uint32_t b1) {
    asm volatile(
        "mma.sync.aligned.m16n8k16.row.col.f32.bf16.bf16.f32 "
        "{%0,%1,%2,%3}, {%4,%5,%6,%7}, {%8,%9}, {%0,%1,%2,%3};"
        : "+f"(c[0]), "+f"(c[1]), "+f"(c[2]), "+f"(c[3])
        : "r"(a0), "r"(a1), "r"(a2), "r"(a3), "r"(b0), "r"(b1));
}

// ---------------- kernel 0: W = W_pos - softplus(W_negraw), split + frag-pack -
__global__ void compute_W_kernel(const float* __restrict__ wp0, const float* __restrict__ wn0,
                                 const float* __restrict__ wp1, const float* __restrict__ wn1,
                                 const float* __restrict__ wp2, const float* __restrict__ wn2) {
    int i = blockIdx.x * blockDim.x + threadIdx.x;
    if (i >= 3 * D * D) return;
    int ty = i / (D * D), r = i % (D * D);
    int k = r / D, n = r % D;
    const float* wp = (ty == 0) ? wp0 : (ty == 1 ? wp1 : wp2);
    const float* wn = (ty == 0) ? wn0 : (ty == 1 ? wn1 : wn2);
    float x = wn[r];
    float sp = fmaxf(x, 0.0f) + log1pf(expf(-fabsf(x)));
    float w = wp[r] - sp;
    __nv_bfloat16 hb = __float2bfloat16(w);
    __nv_bfloat16 lb = __float2bfloat16(w - __bfloat162float(hb));

    int s  = k >> 4;
    int kk = k & 15;
    int reg  = kk >> 3;
    int tq   = (kk >> 1) & 3;
    int half = kk & 1;
    int j    = n >> 3;
    int lane = (n & 7) * 4 + tq;

    unsigned char* slot = (unsigned char*)&g_Wfrag[ty][s][j][lane];
    *(__nv_bfloat16*)(slot + 0 + reg * 4 + half * 2) = hb;
    *(__nv_bfloat16*)(slot + 8 + reg * 4 + half * 2) = lb;
}

// ---------------- kernel 1: zero destination counts --------------------------
__global__ void zero_cnt_kernel(int ndst) {
    int i = blockIdx.x * blockDim.x + threadIdx.x;
    if (i < ndst) g_cnt[i] = 0;
}

// ---------------- kernel 2: fused softmax + split-bf16 HMMA GEMM -------------
#define PROW 136

__global__ void __launch_bounds__(256)
hmma_gemm_kernel(const float* __restrict__ X, int nrows, int t0, int t1) {
    __shared__ __align__(16) __nv_bfloat16 sph[64 * PROW];
    __shared__ __align__(16) __nv_bfloat16 spl[64 * PROW];

    const int tid  = threadIdx.x;
    const int lane = tid & 31;
    const int warp = tid >> 5;
    const int row0 = blockIdx.x * 64;

    #pragma unroll
    for (int r = 0; r < 8; r++) {
        int lrow = warp * 8 + r;
        int row  = row0 + lrow;
        if (row < nrows) {
            const float* xr = X + (size_t)row * D;
            float v[4];
            #pragma unroll
            for (int q = 0; q < 4; q++) v[q] = xr[lane + 32 * q];
            float m = fmaxf(fmaxf(v[0], v[1]), fmaxf(v[2], v[3]));
            #pragma unroll
            for (int o = 16; o > 0; o >>= 1) m = fmaxf(m, __shfl_xor_sync(0xffffffffu, m, o));
            float s = 0.f;
            #pragma unroll
            for (int q = 0; q < 4; q++) { v[q] = expf(v[q] - m); s += v[q]; }
            #pragma unroll
            for (int o = 16; o > 0; o >>= 1) s += __shfl_xor_sync(0xffffffffu, s, o);
            float inv = 1.0f / s;
            #pragma unroll
            for (int q = 0; q < 4; q++) {
                float p = v[q] * inv;
                __nv_bfloat16 hb = __float2bfloat16(p);
                __nv_bfloat16 lb = __float2bfloat16(p - __bfloat162float(hb));
                int col = lane + 32 * q;
                sph[lrow * PROW + col] = hb;
                spl[lrow * PROW + col] = lb;
            }
        } else {
            __nv_bfloat16 z = __float2bfloat16(0.f);
            #pragma unroll
            for (int q = 0; q < 4; q++) {
                int col = lane + 32 * q;
                sph[lrow * PROW + col] = z;
                spl[lrow * PROW + col] = z;
            }
        }
    }
    __syncthreads();

    const int mt = warp >> 1;
    const int nh = warp & 1;
    const int g  = lane >> 2;
    const int tq = lane & 3;

    const uint32_t* ph32 = (const uint32_t*)sph;
    const uint32_t* pl32 = (const uint32_t*)spl;
    const int rbase = (mt * 16 + g) * (PROW / 2);

    const int ntypes = (t1 >= 0) ? 2 : 1;
    for (int tt = 0; tt < ntypes; tt++) {
        const int ty = tt ? t1 : t0;
        const uint4* wf = &g_Wfrag[ty][0][8 * nh][0];

        float acc[32];
        #pragma unroll
        for (int i = 0; i < 32; i++) acc[i] = 0.f;

        #pragma unroll
        for (int s = 0; s < 8; s++) {
            const int o = rbase + 8 * s + tq;
            uint32_t ah0 = ph32[o],           ah2 = ph32[o + 4];
            uint32_t ah1 = ph32[o + 8 * 68],  ah3 = ph32[o + 4 + 8 * 68];
            uint32_t al0 = pl32[o],           al2 = pl32[o + 4];
            uint32_t al1 = pl32[o + 8 * 68],  al3 = pl32[o + 4 + 8 * 68];
            const uint4* wfs = wf + (s * 16) * 32 + lane;
            #pragma unroll
            for (int j = 0; j < 8; j++) {
                uint4 b = wfs[j * 32];
                mma_bf16(acc + 4 * j, ah0, ah1, ah2, ah3, b.x, b.y);
                mma_bf16(acc + 4 * j, al0, al1, al2, al3, b.x, b.y);
                mma_bf16(acc + 4 * j, ah0, ah1, ah2, ah3, b.z, b.w);
            }
        }

        float* Q = g_Q[ty];
        const int rowa = row0 + mt * 16 + g;
        const int rowb = rowa + 8;
        #pragma unroll
        for (int j = 0; j < 8; j++) {
            int cn = 64 * nh + 8 * j + 2 * tq;
            if (rowa < nrows)
                *(float2*)(Q + (size_t)rowa * D + cn) = make_float2(acc[4 * j], acc[4 * j + 1]);
            if (rowb < nrows)
                *(float2*)(Q + (size_t)rowb * D + cn) = make_float2(acc[4 * j + 2], acc[4 * j + 3]);
        }
    }
}

// ---------------- kernel 3: edge placement into per-dst buckets --------------
// slot value: src | (q << 20)  (src < 2^20, q in {0,1,2})
// global dst: A rows [0,NA), B rows [NA, NA+NB)
__global__ void place_kernel(const int* __restrict__ e0, int E0,   // AB: dst B, Q0
                             const int* __restrict__ e1, int E1,   // BA: dst A, Q1
                             const int* __restrict__ e2, int E2,   // AA: dst A, Q2
                             int NA) {
    int i = blockIdx.x * blockDim.x + threadIdx.x;
    int stride = gridDim.x * blockDim.x;
    int ET = E0 + E1 + E2;
    for (int e = i; e < ET; e += stride) {
        int src, gdst; unsigned q;
        if (e < E0)            { src = e0[e];           gdst = NA + e0[E0 + e];      q = 0; }
        else if (e < E0 + E1)  { int le = e - E0;       src = e1[le]; gdst = e1[E1 + le]; q = 1; }
        else                   { int le = e - E0 - E1;  src = e2[le]; gdst = e2[E2 + le]; q = 2; }
        int pos = atomicAdd(&g_cnt[gdst], 1);
        if (pos < CAP) g_bkt[(size_t)gdst * CAP + pos] = (unsigned)src | (q << 20);
    }
}

// ---------------- kernel 4: per-dst gather + register accumulate -------------
// warp per destination row in [base, base+ndst); writes each output row once.
// Launched per dst-range so the Q footprint per pass fits in L2:
//   B-pass reads only Q0 (51MB), A-pass reads Q1+Q2 (102MB).
__global__ void __launch_bounds__(256)
gather_kernel(float* __restrict__ out, int base, int ndst) {
    int gw   = base + ((blockIdx.x * blockDim.x + threadIdx.x) >> 5);
    int lane = threadIdx.x & 31;
    if (gw >= base + ndst) return;

    int cnt = g_cnt[gw];
    cnt = min(cnt, CAP);
    const unsigned* bk = g_bkt + (size_t)gw * CAP;
    const float* Qf = &g_Q[0][0];

    float4 acc = make_float4(0.f, 0.f, 0.f, 0.f);

    int n1 = min(cnt, 32);
    unsigned pk = (lane < n1) ? bk[lane] : 0u;
    for (int e = 0; e < n1; e++) {
        unsigned p = __shfl_sync(0xffffffffu, pk, e);
        const float4* Qr = (const float4*)(Qf + (size_t)(p >> 20) * ((size_t)MAXN * D)
                                              + (size_t)(p & 0xFFFFFu) * D) + lane;
        float4 v = __ldg(Qr);
        acc.x += v.x; acc.y += v.y; acc.z += v.z; acc.w += v.w;
    }
    if (cnt > 32) {
        int n2 = cnt - 32;
        unsigned pk2 = (lane < n2) ? bk[32 + lane] : 0u;
        for (int e = 0; e < n2; e++) {
            unsigned p = __shfl_sync(0xffffffffu, pk2, e);
            const float4* Qr = (const float4*)(Qf + (size_t)(p >> 20) * ((size_t)MAXN * D)
                                                  + (size_t)(p & 0xFFFFFu) * D) + lane;
            float4 v = __ldg(Qr);
            acc.x += v.x; acc.y += v.y; acc.z += v.z; acc.w += v.w;
        }
    }

    *(float4*)(out + (size_t)gw * D + 4 * lane) = acc;
}

// ---------------- launch -----------------------------------------------------
extern "C" void kernel_launch(void* const* d_in, const int* in_sizes, int n_in,
                              void* d_out, int out_size) {
    const float* logits_A = (const float*)d_in[0];
    const float* logits_B = (const float*)d_in[1];
    const int* e_AB = (const int*)d_in[4];
    const int* e_BA = (const int*)d_in[5];
    const int* e_AA = (const int*)d_in[6];
    const float* Wp_AB = (const float*)d_in[7],  *Wn_AB = (const float*)d_in[8];
    const float* Wp_BA = (const float*)d_in[9],  *Wn_BA = (const float*)d_in[10];
    const float* Wp_AA = (const float*)d_in[11], *Wn_AA = (const float*)d_in[12];
    float* out = (float*)d_out;

    const int NA = in_sizes[0] / D;
    const int NB = in_sizes[1] / D;
    const int E_AB = in_sizes[4] / 2;
    const int E_BA = in_sizes[5] / 2;
    const int E_AA = in_sizes[6] / 2;
    const int NDST = NA + NB;
    const int ET = E_AB + E_BA + E_AA;

    compute_W_kernel<<<(3 * D * D + 255) / 256, 256>>>(Wp_AB, Wn_AB, Wp_BA, Wn_BA, Wp_AA, Wn_AA);
    zero_cnt_kernel<<<(NDST + 255) / 256, 256>>>(NDST);
    place_kernel<<<min((ET + 255) / 256, 8192), 256>>>(e_AB, E_AB, e_BA, E_BA, e_AA, E_AA, NA);

    // types 0 (AB) and 2 (AA) share softmax(logits_A) -> one fused kernel
    hmma_gemm_kernel<<<(NA + 63) / 64, 256>>>(logits_A, NA, 0, 2);
    hmma_gemm_kernel<<<(NB + 63) / 64, 256>>>(logits_B, NB, 1, -1);

    // gather split by dst range => per-pass Q footprint fits in L2
    // B-pass first (reads Q0 only), then A-pass (reads Q1+Q2)
    gather_kernel<<<(NB * 32 + 255) / 256, 256>>>(out, NA, NB);
    gather_kernel<<<(NA * 32 + 255) / 256, 256>>>(out, 0, NA);
}

// round 10
// speedup vs baseline: 1.9242x; 1.0373x over previous
#include <cuda_runtime.h>
#include <cuda_bf16.h>
#include <cstdint>

#define D 128
#define MAXN 100000
#define CAP 64          // bucket capacity per destination (Poisson(10): P(>=64) ~ 1e-18)
#define NDST_MAX 200000

// ---------------- device scratch (allocation-free) ---------------------------
// g_Wfrag[type][kstep(8)][ntile(16)][lane(32)] : uint4 = {b0_hi, b1_hi, b0_lo, b1_lo}
__device__ __align__(16) uint4 g_Wfrag[3][8][16][32];
__device__ float g_Q[3][(size_t)MAXN * D];
__device__ int g_cnt[NDST_MAX];
__device__ unsigned g_bkt[(size_t)NDST_MAX * CAP];

// ---------------- mma.sync helper (sm_80+ path, legal on target sm_103) ------
__device__ __forceinline__ void mma_bf16(float* c, uint32_t a0, uint32_t a1,
                                         uint32_t a2, uint32_t a3,
                                         uint32_t b0, uint32_t b1) {
    asm volatile(
        "mma.sync.aligned.m16n8k16.row.col.f32.bf16.bf16.f32 "
        "{%0,%1,%2,%3}, {%4,%5,%6,%7}, {%8,%9}, {%0,%1,%2,%3};"
        : "+f"(c[0]), "+f"(c[1]), "+f"(c[2]), "+f"(c[3])
        : "r"(a0), "r"(a1), "r"(a2), "r"(a3), "r"(b0), "r"(b1));
}

// ---------------- kernel 0: W = W_pos - softplus(W_negraw), split + frag-pack -
__global__ void compute_W_kernel(const float* __restrict__ wp0, const float* __restrict__ wn0,
                                 const float* __restrict__ wp1, const float* __restrict__ wn1,
                                 const float* __restrict__ wp2, const float* __restrict__ wn2) {
    int i = blockIdx.x * blockDim.x + threadIdx.x;
    if (i >= 3 * D * D) return;
    int ty = i / (D * D), r = i % (D * D);
    int k = r / D, n = r % D;
    const float* wp = (ty == 0) ? wp0 : (ty == 1 ? wp1 : wp2);
    const float* wn = (ty == 0) ? wn0 : (ty == 1 ? wn1 : wn2);
    float x = wn[r];
    float sp = fmaxf(x, 0.0f) + log1pf(expf(-fabsf(x)));
    float w = wp[r] - sp;
    __nv_bfloat16 hb = __float2bfloat16(w);
    __nv_bfloat16 lb = __float2bfloat16(w - __bfloat162float(hb));

    int s  = k >> 4;
    int kk = k & 15;
    int reg  = kk >> 3;
    int tq   = (kk >> 1) & 3;
    int half = kk & 1;
    int j    = n >> 3;
    int lane = (n & 7) * 4 + tq;

    unsigned char* slot = (unsigned char*)&g_Wfrag[ty][s][j][lane];
    *(__nv_bfloat16*)(slot + 0 + reg * 4 + half * 2) = hb;
    *(__nv_bfloat16*)(slot + 8 + reg * 4 + half * 2) = lb;
}

// ---------------- kernel 1: zero destination counts --------------------------
__global__ void zero_cnt_kernel(int ndst) {
    int i = blockIdx.x * blockDim.x + threadIdx.x;
    if (i < ndst) g_cnt[i] = 0;
}

// ---------------- kernel 2: fused softmax + split-bf16 HMMA GEMM -------------
// Block = 256 threads (8 warps), 64 rows/CTA; warp -> (mtile, N-half).
// W fragments staged through an 8KB smem buffer per k-step (cooperative
// LDG->STS, register-prefetch of next step overlapped with MMAs).
// Static smem: P 34KB + Wbuf 8KB = 42KB -> 3 CTAs/SM.
#define PROW 136

__global__ void __launch_bounds__(256, 3)
hmma_gemm_kernel(const float* __restrict__ X, int nrows, int t0, int t1) {
    __shared__ __align__(16) __nv_bfloat16 sph[64 * PROW];
    __shared__ __align__(16) __nv_bfloat16 spl[64 * PROW];
    __shared__ __align__(16) uint4 sWb[512];          // 16 j x 32 lanes, one k-step

    const int tid  = threadIdx.x;
    const int lane = tid & 31;
    const int warp = tid >> 5;
    const int row0 = blockIdx.x * 64;

    // ---- softmax: 8 warps x 8 rows each; lane owns 4 cols of its row
    #pragma unroll
    for (int r = 0; r < 8; r++) {
        int lrow = warp * 8 + r;
        int row  = row0 + lrow;
        if (row < nrows) {
            const float* xr = X + (size_t)row * D;
            float v[4];
            #pragma unroll
            for (int q = 0; q < 4; q++) v[q] = xr[lane + 32 * q];
            float m = fmaxf(fmaxf(v[0], v[1]), fmaxf(v[2], v[3]));
            #pragma unroll
            for (int o = 16; o > 0; o >>= 1) m = fmaxf(m, __shfl_xor_sync(0xffffffffu, m, o));
            float s = 0.f;
            #pragma unroll
            for (int q = 0; q < 4; q++) { v[q] = expf(v[q] - m); s += v[q]; }
            #pragma unroll
            for (int o = 16; o > 0; o >>= 1) s += __shfl_xor_sync(0xffffffffu, s, o);
            float inv = 1.0f / s;
            #pragma unroll
            for (int q = 0; q < 4; q++) {
                float p = v[q] * inv;
                __nv_bfloat16 hb = __float2bfloat16(p);
                __nv_bfloat16 lb = __float2bfloat16(p - __bfloat162float(hb));
                int col = lane + 32 * q;
                sph[lrow * PROW + col] = hb;
                spl[lrow * PROW + col] = lb;
            }
        } else {
            __nv_bfloat16 z = __float2bfloat16(0.f);
            #pragma unroll
            for (int q = 0; q < 4; q++) {
                int col = lane + 32 * q;
                sph[lrow * PROW + col] = z;
                spl[lrow * PROW + col] = z;
            }
        }
    }
    __syncthreads();

    const int mt = warp >> 1;
    const int nh = warp & 1;
    const int g  = lane >> 2;
    const int tq = lane & 3;

    const uint32_t* ph32 = (const uint32_t*)sph;
    const uint32_t* pl32 = (const uint32_t*)spl;
    const int rbase = (mt * 16 + g) * (PROW / 2);
    const uint4* bs = &sWb[(8 * nh) * 32 + lane];

    const int ntypes = (t1 >= 0) ? 2 : 1;
    for (int tt = 0; tt < ntypes; tt++) {
        const int ty = tt ? t1 : t0;
        const uint4* wt = &g_Wfrag[ty][0][0][0];

        float acc[32];
        #pragma unroll
        for (int i = 0; i < 32; i++) acc[i] = 0.f;

        // prefetch k-step 0 (2 x LDG.128 per thread; 8KB block is contiguous)
        uint4 p0 = wt[tid], p1 = wt[tid + 256];

        #pragma unroll
        for (int s = 0; s < 8; s++) {
            // stage current k-step into smem
            sWb[tid] = p0;
            sWb[tid + 256] = p1;
            __syncthreads();
            // prefetch next k-step; LDG latency hides under the 24 MMAs below
            if (s < 7) { p0 = wt[(s + 1) * 512 + tid]; p1 = wt[(s + 1) * 512 + tid + 256]; }

            const int o = rbase + 8 * s + tq;
            uint32_t ah0 = ph32[o],           ah2 = ph32[o + 4];
            uint32_t ah1 = ph32[o + 8 * 68],  ah3 = ph32[o + 4 + 8 * 68];
            uint32_t al0 = pl32[o],           al2 = pl32[o + 4];
            uint32_t al1 = pl32[o + 8 * 68],  al3 = pl32[o + 4 + 8 * 68];
            #pragma unroll
            for (int j = 0; j < 8; j++) {
                uint4 b = bs[j * 32];                      // LDS.128, conflict-free
                mma_bf16(acc + 4 * j, ah0, ah1, ah2, ah3, b.x, b.y);   // Ph @ Wh
                mma_bf16(acc + 4 * j, al0, al1, al2, al3, b.x, b.y);   // Pl @ Wh
                mma_bf16(acc + 4 * j, ah0, ah1, ah2, ah3, b.z, b.w);   // Ph @ Wl
            }
            __syncthreads();   // all reads of sWb done before next store
        }

        float* Q = g_Q[ty];
        const int rowa = row0 + mt * 16 + g;
        const int rowb = rowa + 8;
        #pragma unroll
        for (int j = 0; j < 8; j++) {
            int cn = 64 * nh + 8 * j + 2 * tq;
            if (rowa < nrows)
                *(float2*)(Q + (size_t)rowa * D + cn) = make_float2(acc[4 * j], acc[4 * j + 1]);
            if (rowb < nrows)
                *(float2*)(Q + (size_t)rowb * D + cn) = make_float2(acc[4 * j + 2], acc[4 * j + 3]);
        }
    }
}

// ---------------- kernel 3: edge placement into per-dst buckets --------------
// slot value: src | (q << 20)  (src < 2^20, q in {0,1,2})
// global dst: A rows [0,NA), B rows [NA, NA+NB)
__global__ void place_kernel(const int* __restrict__ e0, int E0,   // AB: dst B, Q0
                             const int* __restrict__ e1, int E1,   // BA: dst A, Q1
                             const int* __restrict__ e2, int E2,   // AA: dst A, Q2
                             int NA) {
    int i = blockIdx.x * blockDim.x + threadIdx.x;
    int stride = gridDim.x * blockDim.x;
    int ET = E0 + E1 + E2;
    for (int e = i; e < ET; e += stride) {
        int src, gdst; unsigned q;
        if (e < E0)            { src = e0[e];           gdst = NA + e0[E0 + e];      q = 0; }
        else if (e < E0 + E1)  { int le = e - E0;       src = e1[le]; gdst = e1[E1 + le]; q = 1; }
        else                   { int le = e - E0 - E1;  src = e2[le]; gdst = e2[E2 + le]; q = 2; }
        int pos = atomicAdd(&g_cnt[gdst], 1);
        if (pos < CAP) g_bkt[(size_t)gdst * CAP + pos] = (unsigned)src | (q << 20);
    }
}

// ---------------- kernel 4: per-dst gather + register accumulate -------------
// warp per destination row in [base, base+ndst); writes each output row once.
__global__ void __launch_bounds__(256)
gather_kernel(float* __restrict__ out, int base, int ndst) {
    int gw   = base + ((blockIdx.x * blockDim.x + threadIdx.x) >> 5);
    int lane = threadIdx.x & 31;
    if (gw >= base + ndst) return;

    int cnt = g_cnt[gw];
    cnt = min(cnt, CAP);
    const unsigned* bk = g_bkt + (size_t)gw * CAP;
    const float* Qf = &g_Q[0][0];

    float4 acc = make_float4(0.f, 0.f, 0.f, 0.f);

    int n1 = min(cnt, 32);
    unsigned pk = (lane < n1) ? bk[lane] : 0u;
    for (int e = 0; e < n1; e++) {
        unsigned p = __shfl_sync(0xffffffffu, pk, e);
        const float4* Qr = (const float4*)(Qf + (size_t)(p >> 20) * ((size_t)MAXN * D)
                                              + (size_t)(p & 0xFFFFFu) * D) + lane;
        float4 v = __ldg(Qr);
        acc.x += v.x; acc.y += v.y; acc.z += v.z; acc.w += v.w;
    }
    if (cnt > 32) {
        int n2 = cnt - 32;
        unsigned pk2 = (lane < n2) ? bk[32 + lane] : 0u;
        for (int e = 0; e < n2; e++) {
            unsigned p = __shfl_sync(0xffffffffu, pk2, e);
            const float4* Qr = (const float4*)(Qf + (size_t)(p >> 20) * ((size_t)MAXN * D)
                                                  + (size_t)(p & 0xFFFFFu) * D) + lane;
            float4 v = __ldg(Qr);
            acc.x += v.x; acc.y += v.y; acc.z += v.z; acc.w += v.w;
        }
    }

    *(float4*)(out + (size_t)gw * D + 4 * lane) = acc;
}

// ---------------- launch -----------------------------------------------------
extern "C" void kernel_launch(void* const* d_in, const int* in_sizes, int n_in,
                              void* d_out, int out_size) {
    const float* logits_A = (const float*)d_in[0];
    const float* logits_B = (const float*)d_in[1];
    const int* e_AB = (const int*)d_in[4];
    const int* e_BA = (const int*)d_in[5];
    const int* e_AA = (const int*)d_in[6];
    const float* Wp_AB = (const float*)d_in[7],  *Wn_AB = (const float*)d_in[8];
    const float* Wp_BA = (const float*)d_in[9],  *Wn_BA = (const float*)d_in[10];
    const float* Wp_AA = (const float*)d_in[11], *Wn_AA = (const float*)d_in[12];
    float* out = (float*)d_out;

    const int NA = in_sizes[0] / D;
    const int NB = in_sizes[1] / D;
    const int E_AB = in_sizes[4] / 2;
    const int E_BA = in_sizes[5] / 2;
    const int E_AA = in_sizes[6] / 2;
    const int NDST = NA + NB;
    const int ET = E_AB + E_BA + E_AA;

    compute_W_kernel<<<(3 * D * D + 255) / 256, 256>>>(Wp_AB, Wn_AB, Wp_BA, Wn_BA, Wp_AA, Wn_AA);
    zero_cnt_kernel<<<(NDST + 255) / 256, 256>>>(NDST);
    place_kernel<<<min((ET + 255) / 256, 8192), 256>>>(e_AB, E_AB, e_BA, E_BA, e_AA, E_AA, NA);

    // types 0 (AB) and 2 (AA) share softmax(logits_A) -> one fused kernel
    hmma_gemm_kernel<<<(NA + 63) / 64, 256>>>(logits_A, NA, 0, 2);
    hmma_gemm_kernel<<<(NB + 63) / 64, 256>>>(logits_B, NB, 1, -1);

    // gather split by dst range => per-pass Q footprint fits in L2
    gather_kernel<<<(NB * 32 + 255) / 256, 256>>>(out, NA, NB);
    gather_kernel<<<(NA * 32 + 255) / 256, 256>>>(out, 0, NA);
}